// round 4
// baseline (speedup 1.0000x reference)
#include <cuda_runtime.h>

#define D_MODEL 1024
#define NHEAD 16
#define DK 64
#define BATCH 4
#define SEQ 2048
#define ROWS (BATCH*SEQ)   // 8192

// Scratch (no allocations allowed): q, k, v, attention context
__device__ float g_q[(size_t)ROWS * D_MODEL];
__device__ float g_k[(size_t)ROWS * D_MODEL];
__device__ float g_v[(size_t)ROWS * D_MODEL];
__device__ float g_ctx[(size_t)ROWS * D_MODEL];

// ---------------------------------------------------------------------------
// GEMM: C[m][n] = sum_k A[m][k] * W[n][k]   (x @ W^T, torch-style weights)
// M=8192, N=1024, K=1024. 256 threads compute a 128x128 tile, 8x8 per thread
// (split as 4+4 rows/cols for conflict-free LDS.128). blockIdx.z selects one
// of up to 3 (W, C) pairs so QKV projections run as one launch.
// ---------------------------------------------------------------------------
__global__ __launch_bounds__(256) void gemm_xwt(
    const float* __restrict__ A,
    const float* __restrict__ W0, const float* __restrict__ W1, const float* __restrict__ W2,
    float* __restrict__ C0, float* __restrict__ C1, float* __restrict__ C2)
{
    const int K = D_MODEL, N = D_MODEL;
    const float* W;
    float* C;
    if (blockIdx.z == 0)      { W = W0; C = C0; }
    else if (blockIdx.z == 1) { W = W1; C = C1; }
    else                      { W = W2; C = C2; }

    __shared__ float As[8][132];
    __shared__ float Bs[8][132];

    const int tid = threadIdx.x;
    const int bm = blockIdx.y * 128;
    const int bn = blockIdx.x * 128;
    const int tx = tid & 15, ty = tid >> 4;
    const int r   = tid >> 1;          // 0..127
    const int kk0 = (tid & 1) * 4;     // 0 or 4

    float acc[8][8];
#pragma unroll
    for (int i = 0; i < 8; i++)
#pragma unroll
        for (int j = 0; j < 8; j++) acc[i][j] = 0.f;

    for (int k0 = 0; k0 < K; k0 += 8) {
        float4 va = *(const float4*)(A + (size_t)(bm + r) * K + k0 + kk0);
        float4 vb = *(const float4*)(W + (size_t)(bn + r) * K + k0 + kk0);
        As[kk0 + 0][r] = va.x; As[kk0 + 1][r] = va.y;
        As[kk0 + 2][r] = va.z; As[kk0 + 3][r] = va.w;
        Bs[kk0 + 0][r] = vb.x; Bs[kk0 + 1][r] = vb.y;
        Bs[kk0 + 2][r] = vb.z; Bs[kk0 + 3][r] = vb.w;
        __syncthreads();
#pragma unroll
        for (int kk = 0; kk < 8; kk++) {
            float4 a0 = *(const float4*)&As[kk][ty * 4];
            float4 a1 = *(const float4*)&As[kk][ty * 4 + 64];
            float4 b0 = *(const float4*)&Bs[kk][tx * 4];
            float4 b1 = *(const float4*)&Bs[kk][tx * 4 + 64];
            float a[8] = {a0.x, a0.y, a0.z, a0.w, a1.x, a1.y, a1.z, a1.w};
            float b[8] = {b0.x, b0.y, b0.z, b0.w, b1.x, b1.y, b1.z, b1.w};
#pragma unroll
            for (int i = 0; i < 8; i++)
#pragma unroll
                for (int j = 0; j < 8; j++)
                    acc[i][j] = fmaf(a[i], b[j], acc[i][j]);
        }
        __syncthreads();
    }

#pragma unroll
    for (int i = 0; i < 8; i++) {
        int row = bm + ty * 4 + ((i < 4) ? i : (64 + i - 4));
        float4 v0 = make_float4(acc[i][0], acc[i][1], acc[i][2], acc[i][3]);
        float4 v1 = make_float4(acc[i][4], acc[i][5], acc[i][6], acc[i][7]);
        *(float4*)(C + (size_t)row * N + bn + tx * 4)      = v0;
        *(float4*)(C + (size_t)row * N + bn + tx * 4 + 64) = v1;
    }
}

// ---------------------------------------------------------------------------
// Fused causal attention, flash-style. One CTA = one (b, h, 64-row q tile).
// 256 threads, 4x4 register blocking over 64x64 score / output tiles.
// Smem: Q^T[d][m], K^T[d][n], P^T[n][m], V[n][d] (all padded to 68 floats/row)
// so both GEMM phases read only conflict-free / broadcast LDS.128.
// ---------------------------------------------------------------------------
__global__ __launch_bounds__(256) void attn_fused()
{
    extern __shared__ float sm[];
    float* Qt    = sm;                 // [64][68]  (d, m), pre-scaled by 1/8
    float* Kt    = Qt + 64 * 68;       // [64][68]  (d, n)
    float* Pt    = Kt + 64 * 68;       // [64][68]  (n, m)
    float* Vs    = Pt + 64 * 68;       // [64][68]  (n, dd)
    float* row_m = Vs + 64 * 68;       // [64]
    float* row_l = row_m + 64;         // [64]
    float* row_a = row_l + 64;         // [64]

    const int tid = threadIdx.x;
    const int tx = tid & 15, ty = tid >> 4;
    const int qt = blockIdx.x, h = blockIdx.y, b = blockIdx.z;

    const size_t base = (size_t)b * SEQ * D_MODEL + (size_t)h * DK;
    const float* qg = g_q + base;
    const float* kg = g_k + base;
    const float* vg = g_v + base;

    // Load Q tile transposed, pre-scaled by 1/sqrt(dk)=0.125 (once per CTA)
    for (int idx = tid; idx < 1024; idx += 256) {
        int m = idx >> 4, d4 = idx & 15;
        float4 qv = *(const float4*)(qg + (size_t)(qt * 64 + m) * D_MODEL + d4 * 4);
        Qt[(d4 * 4 + 0) * 68 + m] = qv.x * 0.125f;
        Qt[(d4 * 4 + 1) * 68 + m] = qv.y * 0.125f;
        Qt[(d4 * 4 + 2) * 68 + m] = qv.z * 0.125f;
        Qt[(d4 * 4 + 3) * 68 + m] = qv.w * 0.125f;
    }
    if (tid < 64) { row_m[tid] = -1e30f; row_l[tid] = 0.f; }

    float acco[4][4];
#pragma unroll
    for (int i = 0; i < 4; i++)
#pragma unroll
        for (int j = 0; j < 4; j++) acco[i][j] = 0.f;

    for (int kt = 0; kt <= qt; kt++) {
        __syncthreads();  // previous PV done (and Q/stat init on first iter)

        // Fill K^T and V tiles
        for (int idx = tid; idx < 1024; idx += 256) {
            int n = idx >> 4, d4 = idx & 15;
            float4 kv = *(const float4*)(kg + (size_t)(kt * 64 + n) * D_MODEL + d4 * 4);
            Kt[(d4 * 4 + 0) * 68 + n] = kv.x;
            Kt[(d4 * 4 + 1) * 68 + n] = kv.y;
            Kt[(d4 * 4 + 2) * 68 + n] = kv.z;
            Kt[(d4 * 4 + 3) * 68 + n] = kv.w;
            float4 vv = *(const float4*)(vg + (size_t)(kt * 64 + n) * D_MODEL + d4 * 4);
            *(float4*)&Vs[n * 68 + d4 * 4] = vv;
        }
        __syncthreads();

        // Scores: S[m][n] = sum_d Qt[d][m] * Kt[d][n]
        float accs[4][4];
#pragma unroll
        for (int i = 0; i < 4; i++)
#pragma unroll
            for (int j = 0; j < 4; j++) accs[i][j] = 0.f;
#pragma unroll 8
        for (int d = 0; d < 64; d++) {
            float4 av = *(const float4*)&Qt[d * 68 + ty * 4];
            float4 bv = *(const float4*)&Kt[d * 68 + tx * 4];
            float aa[4] = {av.x, av.y, av.z, av.w};
            float bb[4] = {bv.x, bv.y, bv.z, bv.w};
#pragma unroll
            for (int i = 0; i < 4; i++)
#pragma unroll
                for (int j = 0; j < 4; j++)
                    accs[i][j] = fmaf(aa[i], bb[j], accs[i][j]);
        }

        // Causal mask (diagonal tile only) + store transposed P^T[n][m]
        const bool diag = (kt == qt);
#pragma unroll
        for (int j = 0; j < 4; j++)
#pragma unroll
            for (int i = 0; i < 4; i++) {
                float s = accs[i][j];
                if (diag && (tx * 4 + j) > (ty * 4 + i)) s = -1e30f;
                Pt[(tx * 4 + j) * 68 + (ty * 4 + i)] = s;
            }
        __syncthreads();

        // Online softmax: 4 lanes (a warp quad) per row m
        {
            const int m = tid >> 2, lane = tid & 3;
            float vals[16];
            float mx = -1e30f;
#pragma unroll
            for (int s2 = 0; s2 < 16; s2++) {
                int n = lane * 16 + s2;
                float v = Pt[n * 68 + m];
                vals[s2] = v;
                mx = fmaxf(mx, v);
            }
            mx = fmaxf(mx, __shfl_xor_sync(0xffffffffu, mx, 1));
            mx = fmaxf(mx, __shfl_xor_sync(0xffffffffu, mx, 2));
            float m_old = row_m[m];
            float m_new = fmaxf(m_old, mx);
            float sum = 0.f;
#pragma unroll
            for (int s2 = 0; s2 < 16; s2++) {
                int n = lane * 16 + s2;
                float p = __expf(vals[s2] - m_new);
                Pt[n * 68 + m] = p;
                sum += p;
            }
            sum += __shfl_xor_sync(0xffffffffu, sum, 1);
            sum += __shfl_xor_sync(0xffffffffu, sum, 2);
            if (lane == 0) {
                float alpha = __expf(m_old - m_new);   // 0 on first tile
                row_a[m] = alpha;
                row_l[m] = row_l[m] * alpha + sum;
                row_m[m] = m_new;
            }
        }
        __syncthreads();

        // PV: O[m][dd] += sum_n P^T[n][m] * V[n][dd], with rescale
        float al[4];
#pragma unroll
        for (int i = 0; i < 4; i++) al[i] = row_a[ty * 4 + i];
#pragma unroll
        for (int i = 0; i < 4; i++)
#pragma unroll
            for (int j = 0; j < 4; j++) acco[i][j] *= al[i];
#pragma unroll 8
        for (int n = 0; n < 64; n++) {
            float4 av = *(const float4*)&Pt[n * 68 + ty * 4];
            float4 bv = *(const float4*)&Vs[n * 68 + tx * 4];
            float aa[4] = {av.x, av.y, av.z, av.w};
            float bb[4] = {bv.x, bv.y, bv.z, bv.w};
#pragma unroll
            for (int i = 0; i < 4; i++)
#pragma unroll
                for (int j = 0; j < 4; j++)
                    acco[i][j] = fmaf(aa[i], bb[j], acco[i][j]);
        }
    }

    // Epilogue: normalize and write context (same layout as q/k/v)
    float inv[4];
#pragma unroll
    for (int i = 0; i < 4; i++) inv[i] = 1.f / row_l[ty * 4 + i];
    float* og = g_ctx + base;
#pragma unroll
    for (int i = 0; i < 4; i++) {
        float4 o = make_float4(acco[i][0] * inv[i], acco[i][1] * inv[i],
                               acco[i][2] * inv[i], acco[i][3] * inv[i]);
        *(float4*)(og + (size_t)(qt * 64 + ty * 4 + i) * D_MODEL + tx * 4) = o;
    }
}

// ---------------------------------------------------------------------------
// Launch
// ---------------------------------------------------------------------------
extern "C" void kernel_launch(void* const* d_in, const int* in_sizes, int n_in,
                              void* d_out, int out_size)
{
    (void)in_sizes; (void)n_in; (void)out_size;
    const float* x  = (const float*)d_in[0];
    const float* Wq = (const float*)d_in[1];
    const float* Wk = (const float*)d_in[2];
    const float* Wv = (const float*)d_in[3];
    const float* Wo = (const float*)d_in[4];
    float* out = (float*)d_out;

    float *qp, *kp, *vp, *cp;
    cudaGetSymbolAddress((void**)&qp, g_q);
    cudaGetSymbolAddress((void**)&kp, g_k);
    cudaGetSymbolAddress((void**)&vp, g_v);
    cudaGetSymbolAddress((void**)&cp, g_ctx);

    const int ATTN_SMEM = (4 * 64 * 68 + 3 * 64) * (int)sizeof(float);  // 70400 B
    cudaFuncSetAttribute(attn_fused, cudaFuncAttributeMaxDynamicSharedMemorySize,
                         ATTN_SMEM);

    // Q, K, V projections fused into one grid (z picks the weight)
    dim3 gproj(D_MODEL / 128, ROWS / 128, 3);
    gemm_xwt<<<gproj, 256>>>(x, Wq, Wk, Wv, qp, kp, vp);

    // Causal attention
    dim3 gattn(SEQ / 64, NHEAD, BATCH);
    attn_fused<<<gattn, 256, ATTN_SMEM>>>();

    // Output projection
    dim3 gout(D_MODEL / 128, ROWS / 128, 1);
    gemm_xwt<<<gout, 256>>>(cp, Wo, Wo, Wo, out, out, out);
}

// round 5
// speedup vs baseline: 1.4902x; 1.4902x over previous
#include <cuda_runtime.h>
#include <cstdint>

#define D_MODEL 1024
#define NHEAD 16
#define DK 64
#define BATCH 4
#define SEQ 2048
#define ROWS (BATCH*SEQ)   // 8192

// Scratch (no allocations allowed): q, k, v, attention context
__device__ float g_q[(size_t)ROWS * D_MODEL];
__device__ float g_k[(size_t)ROWS * D_MODEL];
__device__ float g_v[(size_t)ROWS * D_MODEL];
__device__ float g_ctx[(size_t)ROWS * D_MODEL];

// ---------------------------------------------------------------------------
// TF32 tensor-core GEMM: C[m][n] = sum_k A[m][k] * W[n][k]  (x @ W^T)
// M=8192, N=1024, K=1024. CTA = 128x128 tile, 8 warps, warp tile 32x64,
// mma.sync.m16n8k8.tf32, double-buffered smem, natural [m][k] layout with
// 36-word pitch (conflict-free fragment loads: bank = 4m+k unique).
// blockIdx.z selects one of up to 3 (W, C) pairs (QKV in one launch).
// ---------------------------------------------------------------------------
#define LDA 36
#define TILEW (128*LDA)     // words per operand tile
#define BUFW  (2*TILEW)     // A+B per buffer
#define GEMM_SMEM (2*BUFW*4)  // 73728 bytes

__device__ __forceinline__ uint32_t f2tf32(float x) {
    uint32_t u;
    asm("cvt.rna.tf32.f32 %0, %1;" : "=r"(u) : "f"(x));
    return u;
}

__device__ __forceinline__ void mma8(float* c, const uint32_t* a,
                                     uint32_t b0, uint32_t b1) {
    asm volatile(
        "mma.sync.aligned.m16n8k8.row.col.f32.tf32.tf32.f32 "
        "{%0,%1,%2,%3}, {%4,%5,%6,%7}, {%8,%9}, {%0,%1,%2,%3};"
        : "+f"(c[0]), "+f"(c[1]), "+f"(c[2]), "+f"(c[3])
        : "r"(a[0]), "r"(a[1]), "r"(a[2]), "r"(a[3]), "r"(b0), "r"(b1));
}

__global__ __launch_bounds__(256, 2) void gemm_tf32(
    const float* __restrict__ A,
    const float* __restrict__ W0, const float* __restrict__ W1, const float* __restrict__ W2,
    float* __restrict__ C0, float* __restrict__ C1, float* __restrict__ C2)
{
    extern __shared__ uint32_t sm[];
    const float* W;
    float* C;
    if (blockIdx.z == 0)      { W = W0; C = C0; }
    else if (blockIdx.z == 1) { W = W1; C = C1; }
    else                      { W = W2; C = C2; }

    const int tid  = threadIdx.x;
    const int bm   = blockIdx.y * 128;
    const int bn   = blockIdx.x * 128;
    const int w    = tid >> 5, lane = tid & 31;
    const int g    = lane >> 2, t = lane & 3;
    const int wm   = (w & 3) * 32;
    const int wn   = (w >> 2) * 64;

    // Fill mapping: thread -> (row mf, starting element kf), 4 float4 per tile
    const int mf = tid >> 1;
    const int kf = (tid & 1) * 4;
    const float* Ap = A + (size_t)(bm + mf) * D_MODEL + kf;
    const float* Wp = W + (size_t)(bn + mf) * D_MODEL + kf;
    uint32_t* Af = sm + mf * LDA + kf;
    uint32_t* Bf = sm + TILEW + mf * LDA + kf;

    float acc[2][8][4];
#pragma unroll
    for (int i = 0; i < 2; i++)
#pragma unroll
        for (int j = 0; j < 8; j++)
#pragma unroll
            for (int q = 0; q < 4; q++) acc[i][j][q] = 0.f;

    float4 ra[4], rb[4];

    auto LOAD = [&](int c) {
#pragma unroll
        for (int i = 0; i < 4; i++) {
            ra[i] = *(const float4*)(Ap + c * 32 + i * 8);
            rb[i] = *(const float4*)(Wp + c * 32 + i * 8);
        }
    };
    auto STORE = [&](int buf) {
#pragma unroll
        for (int i = 0; i < 4; i++) {
            uint4 ua = make_uint4(f2tf32(ra[i].x), f2tf32(ra[i].y),
                                  f2tf32(ra[i].z), f2tf32(ra[i].w));
            uint4 ub = make_uint4(f2tf32(rb[i].x), f2tf32(rb[i].y),
                                  f2tf32(rb[i].z), f2tf32(rb[i].w));
            *(uint4*)(Af + buf * BUFW + i * 8) = ua;
            *(uint4*)(Bf + buf * BUFW + i * 8) = ub;
        }
    };
    auto COMPUTE = [&](int buf) {
        const uint32_t* Ab = sm + buf * BUFW;
        const uint32_t* Bb = sm + buf * BUFW + TILEW;
#pragma unroll
        for (int st = 0; st < 4; st++) {
            uint32_t af[2][4];
#pragma unroll
            for (int i = 0; i < 2; i++) {
                const uint32_t* p = Ab + (wm + i * 16 + g) * LDA + st * 8 + t;
                af[i][0] = p[0];
                af[i][1] = p[8 * LDA];
                af[i][2] = p[4];
                af[i][3] = p[8 * LDA + 4];
            }
#pragma unroll
            for (int j = 0; j < 8; j++) {
                const uint32_t* p = Bb + (wn + j * 8 + g) * LDA + st * 8 + t;
                uint32_t b0 = p[0], b1 = p[4];
                mma8(acc[0][j], af[0], b0, b1);
                mma8(acc[1][j], af[1], b0, b1);
            }
        }
    };

    LOAD(0);
    STORE(0);
    __syncthreads();
    const int NCH = D_MODEL / 32;
    for (int c = 0; c < NCH; c++) {
        if (c + 1 < NCH) LOAD(c + 1);
        COMPUTE(c & 1);
        if (c + 1 < NCH) STORE((c + 1) & 1);
        __syncthreads();
    }

    // Epilogue: c0:(g,2t) c1:(g,2t+1) c2:(g+8,2t) c3:(g+8,2t+1)
#pragma unroll
    for (int i = 0; i < 2; i++) {
        int r0 = bm + wm + i * 16 + g;
#pragma unroll
        for (int j = 0; j < 8; j++) {
            int col = bn + wn + j * 8 + 2 * t;
            *(float2*)(C + (size_t)r0 * D_MODEL + col) =
                make_float2(acc[i][j][0], acc[i][j][1]);
            *(float2*)(C + (size_t)(r0 + 8) * D_MODEL + col) =
                make_float2(acc[i][j][2], acc[i][j][3]);
        }
    }
}

// ---------------------------------------------------------------------------
// Fused causal attention, flash-style (unchanged fp32 path this round).
// ---------------------------------------------------------------------------
__global__ __launch_bounds__(256) void attn_fused()
{
    extern __shared__ float smf[];
    float* Qt    = smf;                // [64][68]  (d, m), pre-scaled by 1/8
    float* Kt    = Qt + 64 * 68;       // [64][68]  (d, n)
    float* Pt    = Kt + 64 * 68;       // [64][68]  (n, m)
    float* Vs    = Pt + 64 * 68;       // [64][68]  (n, dd)
    float* row_m = Vs + 64 * 68;       // [64]
    float* row_l = row_m + 64;         // [64]
    float* row_a = row_l + 64;         // [64]

    const int tid = threadIdx.x;
    const int tx = tid & 15, ty = tid >> 4;
    const int qt = blockIdx.x, h = blockIdx.y, b = blockIdx.z;

    const size_t base = (size_t)b * SEQ * D_MODEL + (size_t)h * DK;
    const float* qg = g_q + base;
    const float* kg = g_k + base;
    const float* vg = g_v + base;

    for (int idx = tid; idx < 1024; idx += 256) {
        int m = idx >> 4, d4 = idx & 15;
        float4 qv = *(const float4*)(qg + (size_t)(qt * 64 + m) * D_MODEL + d4 * 4);
        Qt[(d4 * 4 + 0) * 68 + m] = qv.x * 0.125f;
        Qt[(d4 * 4 + 1) * 68 + m] = qv.y * 0.125f;
        Qt[(d4 * 4 + 2) * 68 + m] = qv.z * 0.125f;
        Qt[(d4 * 4 + 3) * 68 + m] = qv.w * 0.125f;
    }
    if (tid < 64) { row_m[tid] = -1e30f; row_l[tid] = 0.f; }

    float acco[4][4];
#pragma unroll
    for (int i = 0; i < 4; i++)
#pragma unroll
        for (int j = 0; j < 4; j++) acco[i][j] = 0.f;

    for (int kt = 0; kt <= qt; kt++) {
        __syncthreads();

        for (int idx = tid; idx < 1024; idx += 256) {
            int n = idx >> 4, d4 = idx & 15;
            float4 kv = *(const float4*)(kg + (size_t)(kt * 64 + n) * D_MODEL + d4 * 4);
            Kt[(d4 * 4 + 0) * 68 + n] = kv.x;
            Kt[(d4 * 4 + 1) * 68 + n] = kv.y;
            Kt[(d4 * 4 + 2) * 68 + n] = kv.z;
            Kt[(d4 * 4 + 3) * 68 + n] = kv.w;
            float4 vv = *(const float4*)(vg + (size_t)(kt * 64 + n) * D_MODEL + d4 * 4);
            *(float4*)&Vs[n * 68 + d4 * 4] = vv;
        }
        __syncthreads();

        float accs[4][4];
#pragma unroll
        for (int i = 0; i < 4; i++)
#pragma unroll
            for (int j = 0; j < 4; j++) accs[i][j] = 0.f;
#pragma unroll 8
        for (int d = 0; d < 64; d++) {
            float4 av = *(const float4*)&Qt[d * 68 + ty * 4];
            float4 bv = *(const float4*)&Kt[d * 68 + tx * 4];
            float aa[4] = {av.x, av.y, av.z, av.w};
            float bb[4] = {bv.x, bv.y, bv.z, bv.w};
#pragma unroll
            for (int i = 0; i < 4; i++)
#pragma unroll
                for (int j = 0; j < 4; j++)
                    accs[i][j] = fmaf(aa[i], bb[j], accs[i][j]);
        }

        const bool diag = (kt == qt);
#pragma unroll
        for (int j = 0; j < 4; j++)
#pragma unroll
            for (int i = 0; i < 4; i++) {
                float s = accs[i][j];
                if (diag && (tx * 4 + j) > (ty * 4 + i)) s = -1e30f;
                Pt[(tx * 4 + j) * 68 + (ty * 4 + i)] = s;
            }
        __syncthreads();

        {
            const int m = tid >> 2, lane = tid & 3;
            float vals[16];
            float mx = -1e30f;
#pragma unroll
            for (int s2 = 0; s2 < 16; s2++) {
                int n = lane * 16 + s2;
                float v = Pt[n * 68 + m];
                vals[s2] = v;
                mx = fmaxf(mx, v);
            }
            mx = fmaxf(mx, __shfl_xor_sync(0xffffffffu, mx, 1));
            mx = fmaxf(mx, __shfl_xor_sync(0xffffffffu, mx, 2));
            float m_old = row_m[m];
            float m_new = fmaxf(m_old, mx);
            float sum = 0.f;
#pragma unroll
            for (int s2 = 0; s2 < 16; s2++) {
                int n = lane * 16 + s2;
                float p = __expf(vals[s2] - m_new);
                Pt[n * 68 + m] = p;
                sum += p;
            }
            sum += __shfl_xor_sync(0xffffffffu, sum, 1);
            sum += __shfl_xor_sync(0xffffffffu, sum, 2);
            if (lane == 0) {
                float alpha = __expf(m_old - m_new);
                row_a[m] = alpha;
                row_l[m] = row_l[m] * alpha + sum;
                row_m[m] = m_new;
            }
        }
        __syncthreads();

        float al[4];
#pragma unroll
        for (int i = 0; i < 4; i++) al[i] = row_a[ty * 4 + i];
#pragma unroll
        for (int i = 0; i < 4; i++)
#pragma unroll
            for (int j = 0; j < 4; j++) acco[i][j] *= al[i];
#pragma unroll 8
        for (int n = 0; n < 64; n++) {
            float4 av = *(const float4*)&Pt[n * 68 + ty * 4];
            float4 bv = *(const float4*)&Vs[n * 68 + tx * 4];
            float aa[4] = {av.x, av.y, av.z, av.w};
            float bb[4] = {bv.x, bv.y, bv.z, bv.w};
#pragma unroll
            for (int i = 0; i < 4; i++)
#pragma unroll
                for (int j = 0; j < 4; j++)
                    acco[i][j] = fmaf(aa[i], bb[j], acco[i][j]);
        }
    }

    float inv[4];
#pragma unroll
    for (int i = 0; i < 4; i++) inv[i] = 1.f / row_l[ty * 4 + i];
    float* og = g_ctx + base;
#pragma unroll
    for (int i = 0; i < 4; i++) {
        float4 o = make_float4(acco[i][0] * inv[i], acco[i][1] * inv[i],
                               acco[i][2] * inv[i], acco[i][3] * inv[i]);
        *(float4*)(og + (size_t)(qt * 64 + ty * 4 + i) * D_MODEL + tx * 4) = o;
    }
}

// ---------------------------------------------------------------------------
// Launch
// ---------------------------------------------------------------------------
extern "C" void kernel_launch(void* const* d_in, const int* in_sizes, int n_in,
                              void* d_out, int out_size)
{
    (void)in_sizes; (void)n_in; (void)out_size;
    const float* x  = (const float*)d_in[0];
    const float* Wq = (const float*)d_in[1];
    const float* Wk = (const float*)d_in[2];
    const float* Wv = (const float*)d_in[3];
    const float* Wo = (const float*)d_in[4];
    float* out = (float*)d_out;

    float *qp, *kp, *vp, *cp;
    cudaGetSymbolAddress((void**)&qp, g_q);
    cudaGetSymbolAddress((void**)&kp, g_k);
    cudaGetSymbolAddress((void**)&vp, g_v);
    cudaGetSymbolAddress((void**)&cp, g_ctx);

    const int ATTN_SMEM = (4 * 64 * 68 + 3 * 64) * (int)sizeof(float);  // 70400 B
    cudaFuncSetAttribute(attn_fused, cudaFuncAttributeMaxDynamicSharedMemorySize,
                         ATTN_SMEM);
    cudaFuncSetAttribute(gemm_tf32, cudaFuncAttributeMaxDynamicSharedMemorySize,
                         GEMM_SMEM);

    // Q, K, V projections fused into one grid (z picks the weight)
    dim3 gproj(D_MODEL / 128, ROWS / 128, 3);
    gemm_tf32<<<gproj, 256, GEMM_SMEM>>>(x, Wq, Wk, Wv, qp, kp, vp);

    // Causal attention
    dim3 gattn(SEQ / 64, NHEAD, BATCH);
    attn_fused<<<gattn, 256, ATTN_SMEM>>>();

    // Output projection
    dim3 gout(D_MODEL / 128, ROWS / 128, 1);
    gemm_tf32<<<gout, 256, GEMM_SMEM>>>(cp, Wo, Wo, Wo, out, out, out);
}

// round 9
// speedup vs baseline: 1.6859x; 1.1314x over previous
#include <cuda_runtime.h>
#include <cstdint>

#define D_MODEL 1024
#define NHEAD 16
#define DK 64
#define BATCH 4
#define SEQ 2048
#define ROWS (BATCH*SEQ)   // 8192

// Scratch (no allocations allowed): q, k, v, attention context
__device__ float g_q[(size_t)ROWS * D_MODEL];
__device__ float g_k[(size_t)ROWS * D_MODEL];
__device__ float g_v[(size_t)ROWS * D_MODEL];
__device__ float g_ctx[(size_t)ROWS * D_MODEL];

__device__ __forceinline__ uint32_t f2tf32(float x) {
    uint32_t u;
    asm("cvt.rna.tf32.f32 %0, %1;" : "=r"(u) : "f"(x));
    return u;
}

__device__ __forceinline__ void mma8(float* c, const uint32_t* a,
                                     uint32_t b0, uint32_t b1) {
    asm volatile(
        "mma.sync.aligned.m16n8k8.row.col.f32.tf32.tf32.f32 "
        "{%0,%1,%2,%3}, {%4,%5,%6,%7}, {%8,%9}, {%0,%1,%2,%3};"
        : "+f"(c[0]), "+f"(c[1]), "+f"(c[2]), "+f"(c[3])
        : "r"(a[0]), "r"(a[1]), "r"(a[2]), "r"(a[3]), "r"(b0), "r"(b1));
}

// ---------------------------------------------------------------------------
// TF32 tensor-core GEMM: C[m][n] = sum_k A[m][k] * W[n][k]  (x @ W^T)
// (unchanged from round 5)
// ---------------------------------------------------------------------------
#define LDA 36
#define TILEW (128*LDA)
#define BUFW  (2*TILEW)
#define GEMM_SMEM (2*BUFW*4)

__global__ __launch_bounds__(256, 2) void gemm_tf32(
    const float* __restrict__ A,
    const float* __restrict__ W0, const float* __restrict__ W1, const float* __restrict__ W2,
    float* __restrict__ C0, float* __restrict__ C1, float* __restrict__ C2)
{
    extern __shared__ uint32_t sm[];
    const float* W;
    float* C;
    if (blockIdx.z == 0)      { W = W0; C = C0; }
    else if (blockIdx.z == 1) { W = W1; C = C1; }
    else                      { W = W2; C = C2; }

    const int tid  = threadIdx.x;
    const int bm   = blockIdx.y * 128;
    const int bn   = blockIdx.x * 128;
    const int w    = tid >> 5, lane = tid & 31;
    const int g    = lane >> 2, t = lane & 3;
    const int wm   = (w & 3) * 32;
    const int wn   = (w >> 2) * 64;

    const int mf = tid >> 1;
    const int kf = (tid & 1) * 4;
    const float* Ap = A + (size_t)(bm + mf) * D_MODEL + kf;
    const float* Wp = W + (size_t)(bn + mf) * D_MODEL + kf;
    uint32_t* Af = sm + mf * LDA + kf;
    uint32_t* Bf = sm + TILEW + mf * LDA + kf;

    float acc[2][8][4];
#pragma unroll
    for (int i = 0; i < 2; i++)
#pragma unroll
        for (int j = 0; j < 8; j++)
#pragma unroll
            for (int q = 0; q < 4; q++) acc[i][j][q] = 0.f;

    float4 ra[4], rb[4];

    auto LOAD = [&](int c) {
#pragma unroll
        for (int i = 0; i < 4; i++) {
            ra[i] = *(const float4*)(Ap + c * 32 + i * 8);
            rb[i] = *(const float4*)(Wp + c * 32 + i * 8);
        }
    };
    auto STORE = [&](int buf) {
#pragma unroll
        for (int i = 0; i < 4; i++) {
            uint4 ua = make_uint4(f2tf32(ra[i].x), f2tf32(ra[i].y),
                                  f2tf32(ra[i].z), f2tf32(ra[i].w));
            uint4 ub = make_uint4(f2tf32(rb[i].x), f2tf32(rb[i].y),
                                  f2tf32(rb[i].z), f2tf32(rb[i].w));
            *(uint4*)(Af + buf * BUFW + i * 8) = ua;
            *(uint4*)(Bf + buf * BUFW + i * 8) = ub;
        }
    };
    auto COMPUTE = [&](int buf) {
        const uint32_t* Ab = sm + buf * BUFW;
        const uint32_t* Bb = sm + buf * BUFW + TILEW;
#pragma unroll
        for (int st = 0; st < 4; st++) {
            uint32_t af[2][4];
#pragma unroll
            for (int i = 0; i < 2; i++) {
                const uint32_t* p = Ab + (wm + i * 16 + g) * LDA + st * 8 + t;
                af[i][0] = p[0];
                af[i][1] = p[8 * LDA];
                af[i][2] = p[4];
                af[i][3] = p[8 * LDA + 4];
            }
#pragma unroll
            for (int j = 0; j < 8; j++) {
                const uint32_t* p = Bb + (wn + j * 8 + g) * LDA + st * 8 + t;
                uint32_t b0 = p[0], b1 = p[4];
                mma8(acc[0][j], af[0], b0, b1);
                mma8(acc[1][j], af[1], b0, b1);
            }
        }
    };

    LOAD(0);
    STORE(0);
    __syncthreads();
    const int NCH = D_MODEL / 32;
    for (int c = 0; c < NCH; c++) {
        if (c + 1 < NCH) LOAD(c + 1);
        COMPUTE(c & 1);
        if (c + 1 < NCH) STORE((c + 1) & 1);
        __syncthreads();
    }

#pragma unroll
    for (int i = 0; i < 2; i++) {
        int r0 = bm + wm + i * 16 + g;
#pragma unroll
        for (int j = 0; j < 8; j++) {
            int col = bn + wn + j * 8 + 2 * t;
            *(float2*)(C + (size_t)r0 * D_MODEL + col) =
                make_float2(acc[i][j][0], acc[i][j][1]);
            *(float2*)(C + (size_t)(r0 + 8) * D_MODEL + col) =
                make_float2(acc[i][j][2], acc[i][j][3]);
        }
    }
}

// ---------------------------------------------------------------------------
// Fused causal attention on tf32 tensor cores. One CTA = (b, h, 64 q rows).
// 4 warps; warp w owns score rows [w*16, w*16+16) for the whole kt loop:
// softmax runs in registers (quad shuffles), O accumulators in registers.
// Smem tiles pitch 68 words -> conflict-free mma fragment loads (bank=4g+t).
// ---------------------------------------------------------------------------
#define AP 68
#define ATTN_SMEM (4*64*AP*4)   // 69632 bytes

__global__ __launch_bounds__(128, 3) void attn_tc()
{
    extern __shared__ uint32_t sm[];
    uint32_t* Qs = sm;               // [64][AP] tf32, pre-scaled by 0.125
    uint32_t* Ks = sm + 64 * AP;     // [64][AP] tf32, natural [n][k]
    uint32_t* Ps = sm + 2 * 64 * AP; // [64][AP] tf32, P[m][n]
    uint32_t* Vt = sm + 3 * 64 * AP; // [64][AP] tf32, transposed [dd][n]

    const int tid = threadIdx.x;
    const int w = tid >> 5, lane = tid & 31;
    const int g = lane >> 2, t = lane & 3;
    const int qt = blockIdx.x, h = blockIdx.y, b = blockIdx.z;

    const size_t base = (size_t)b * SEQ * D_MODEL + (size_t)h * DK;
    const float* qg = g_q + base;
    const float* kg = g_k + base;
    const float* vg = g_v + base;

    // Load Q tile (natural [m][k]), scale by 1/sqrt(dk)=0.125, cvt tf32
    for (int idx = tid; idx < 1024; idx += 128) {
        int m = idx >> 4, c4 = idx & 15;
        float4 qv = *(const float4*)(qg + (size_t)(qt * 64 + m) * D_MODEL + c4 * 4);
        *(uint4*)(Qs + m * AP + c4 * 4) =
            make_uint4(f2tf32(qv.x * 0.125f), f2tf32(qv.y * 0.125f),
                       f2tf32(qv.z * 0.125f), f2tf32(qv.w * 0.125f));
    }

    const int rowA = w * 16 + g;      // this thread's first row (c0,c1)
                                       // second row = rowA + 8 (c2,c3)
    float mr[2] = {-1e30f, -1e30f};
    float lr[2] = {0.f, 0.f};
    float acco[8][4];
#pragma unroll
    for (int j = 0; j < 8; j++)
#pragma unroll
        for (int q = 0; q < 4; q++) acco[j][q] = 0.f;

    // Fragment base pointers
    const uint32_t* qfb = Qs + rowA * AP + t;
    const uint32_t* kfb = Ks + g * AP + t;
    const uint32_t* pfb = Ps + rowA * AP + t;
    const uint32_t* vfb = Vt + g * AP + t;
    uint32_t* psb = Ps + rowA * AP;

    for (int kt = 0; kt <= qt; kt++) {
        __syncthreads();   // previous iteration fully done with Ks/Vt

        // Fill K tile (natural) — straight float4 copy + cvt
        for (int idx = tid; idx < 1024; idx += 128) {
            int n = idx >> 4, c4 = idx & 15;
            float4 kv = *(const float4*)(kg + (size_t)(kt * 64 + n) * D_MODEL + c4 * 4);
            *(uint4*)(Ks + n * AP + c4 * 4) =
                make_uint4(f2tf32(kv.x), f2tf32(kv.y), f2tf32(kv.z), f2tf32(kv.w));
        }
        // Fill V transposed via per-thread 4x4 register blocks
        for (int it = 0; it < 2; it++) {
            int bidx = tid + it * 128;       // 0..255
            int dd4 = bidx & 15;             // float4 group along dd
            int ng = bidx >> 4;              // n group (4 rows)
            float4 r[4];
#pragma unroll
            for (int i = 0; i < 4; i++)
                r[i] = *(const float4*)(vg + (size_t)(kt * 64 + ng * 4 + i) * D_MODEL + dd4 * 4);
            float* rf = (float*)r;
#pragma unroll
            for (int u = 0; u < 4; u++) {
                *(uint4*)(Vt + (dd4 * 4 + u) * AP + ng * 4) =
                    make_uint4(f2tf32(rf[0 * 4 + u]), f2tf32(rf[1 * 4 + u]),
                               f2tf32(rf[2 * 4 + u]), f2tf32(rf[3 * 4 + u]));
            }
        }
        __syncthreads();

        // ---- S = Q K^T (64x64 per CTA, 16x64 per warp) ----
        float accs[8][4];
#pragma unroll
        for (int j = 0; j < 8; j++)
#pragma unroll
            for (int q = 0; q < 4; q++) accs[j][q] = 0.f;
#pragma unroll
        for (int kc = 0; kc < 8; kc++) {
            uint32_t a[4];
            a[0] = qfb[kc * 8];
            a[1] = qfb[8 * AP + kc * 8];
            a[2] = qfb[kc * 8 + 4];
            a[3] = qfb[8 * AP + kc * 8 + 4];
#pragma unroll
            for (int j = 0; j < 8; j++) {
                const uint32_t* bp = kfb + (j * 8) * AP + kc * 8;
                mma8(accs[j], a, bp[0], bp[4]);
            }
        }

        // ---- causal mask on diagonal tile ----
        if (kt == qt) {
#pragma unroll
            for (int j = 0; j < 8; j++) {
                int c = j * 8 + 2 * t;
                if (c > rowA)     accs[j][0] = -1e30f;
                if (c + 1 > rowA) accs[j][1] = -1e30f;
                if (c > rowA + 8)     accs[j][2] = -1e30f;
                if (c + 1 > rowA + 8) accs[j][3] = -1e30f;
            }
        }

        // ---- online softmax in registers (quad = 4 lanes sharing rows) ----
        float mxA = -1e30f, mxB = -1e30f;
#pragma unroll
        for (int j = 0; j < 8; j++) {
            mxA = fmaxf(mxA, fmaxf(accs[j][0], accs[j][1]));
            mxB = fmaxf(mxB, fmaxf(accs[j][2], accs[j][3]));
        }
        mxA = fmaxf(mxA, __shfl_xor_sync(0xffffffffu, mxA, 1));
        mxA = fmaxf(mxA, __shfl_xor_sync(0xffffffffu, mxA, 2));
        mxB = fmaxf(mxB, __shfl_xor_sync(0xffffffffu, mxB, 1));
        mxB = fmaxf(mxB, __shfl_xor_sync(0xffffffffu, mxB, 2));

        float mnA = fmaxf(mr[0], mxA), mnB = fmaxf(mr[1], mxB);
        float alA = __expf(mr[0] - mnA), alB = __expf(mr[1] - mnB);
        mr[0] = mnA; mr[1] = mnB;

        float sA = 0.f, sB = 0.f;
#pragma unroll
        for (int j = 0; j < 8; j++) {
            accs[j][0] = __expf(accs[j][0] - mnA);
            accs[j][1] = __expf(accs[j][1] - mnA);
            accs[j][2] = __expf(accs[j][2] - mnB);
            accs[j][3] = __expf(accs[j][3] - mnB);
            sA += accs[j][0] + accs[j][1];
            sB += accs[j][2] + accs[j][3];
        }
        sA += __shfl_xor_sync(0xffffffffu, sA, 1);
        sA += __shfl_xor_sync(0xffffffffu, sA, 2);
        sB += __shfl_xor_sync(0xffffffffu, sB, 1);
        sB += __shfl_xor_sync(0xffffffffu, sB, 2);
        lr[0] = lr[0] * alA + sA;
        lr[1] = lr[1] * alB + sB;

        // rescale O accumulators
#pragma unroll
        for (int j = 0; j < 8; j++) {
            acco[j][0] *= alA; acco[j][1] *= alA;
            acco[j][2] *= alB; acco[j][3] *= alB;
        }

        // store P (own rows only) as tf32
#pragma unroll
        for (int j = 0; j < 8; j++) {
            *(uint2*)(psb + j * 8 + 2 * t) =
                make_uint2(f2tf32(accs[j][0]), f2tf32(accs[j][1]));
            *(uint2*)(psb + 8 * AP + j * 8 + 2 * t) =
                make_uint2(f2tf32(accs[j][2]), f2tf32(accs[j][3]));
        }
        __syncwarp();

        // ---- O += P V  (A = P own rows, B = Vt) ----
#pragma unroll
        for (int kc = 0; kc < 8; kc++) {
            uint32_t a[4];
            a[0] = pfb[kc * 8];
            a[1] = pfb[8 * AP + kc * 8];
            a[2] = pfb[kc * 8 + 4];
            a[3] = pfb[8 * AP + kc * 8 + 4];
#pragma unroll
            for (int j = 0; j < 8; j++) {
                const uint32_t* bp = vfb + (j * 8) * AP + kc * 8;
                mma8(acco[j], a, bp[0], bp[4]);
            }
        }
        __syncwarp();   // done reading Ps before next iteration overwrites
    }

    // Epilogue: normalize and write context
    float invA = 1.f / lr[0], invB = 1.f / lr[1];
    float* og = g_ctx + base;
    size_t rA = (size_t)(qt * 64 + rowA) * D_MODEL;
    size_t rB = (size_t)(qt * 64 + rowA + 8) * D_MODEL;
#pragma unroll
    for (int j = 0; j < 8; j++) {
        int col = j * 8 + 2 * t;
        *(float2*)(og + rA + col) = make_float2(acco[j][0] * invA, acco[j][1] * invA);
        *(float2*)(og + rB + col) = make_float2(acco[j][2] * invB, acco[j][3] * invB);
    }
}

// ---------------------------------------------------------------------------
// Launch
// ---------------------------------------------------------------------------
extern "C" void kernel_launch(void* const* d_in, const int* in_sizes, int n_in,
                              void* d_out, int out_size)
{
    (void)in_sizes; (void)n_in; (void)out_size;
    const float* x  = (const float*)d_in[0];
    const float* Wq = (const float*)d_in[1];
    const float* Wk = (const float*)d_in[2];
    const float* Wv = (const float*)d_in[3];
    const float* Wo = (const float*)d_in[4];
    float* out = (float*)d_out;

    float *qp, *kp, *vp, *cp;
    cudaGetSymbolAddress((void**)&qp, g_q);
    cudaGetSymbolAddress((void**)&kp, g_k);
    cudaGetSymbolAddress((void**)&vp, g_v);
    cudaGetSymbolAddress((void**)&cp, g_ctx);

    cudaFuncSetAttribute(gemm_tf32, cudaFuncAttributeMaxDynamicSharedMemorySize,
                         GEMM_SMEM);
    cudaFuncSetAttribute(attn_tc, cudaFuncAttributeMaxDynamicSharedMemorySize,
                         ATTN_SMEM);

    // Q, K, V projections fused into one grid (z picks the weight)
    dim3 gproj(D_MODEL / 128, ROWS / 128, 3);
    gemm_tf32<<<gproj, 256, GEMM_SMEM>>>(x, Wq, Wk, Wv, qp, kp, vp);

    // Causal attention (tf32 tensor cores)
    dim3 gattn(SEQ / 64, NHEAD, BATCH);
    attn_tc<<<gattn, 128, ATTN_SMEM>>>();

    // Output projection
    dim3 gout(D_MODEL / 128, ROWS / 128, 1);
    gemm_tf32<<<gout, 256, GEMM_SMEM>>>(cp, Wo, Wo, Wo, out, out, out);
}

// round 12
// speedup vs baseline: 3.6789x; 2.1822x over previous
#include <cuda_runtime.h>
#include <cstdint>

#define D_MODEL 1024
#define NHEAD 16
#define DK 64
#define BATCH 4
#define SEQ 2048
#define ROWS (BATCH*SEQ)   // 8192

// Scratch (no allocations allowed)
__device__ float g_q[(size_t)ROWS * D_MODEL];
__device__ float g_k[(size_t)ROWS * D_MODEL];
__device__ float g_v[(size_t)ROWS * D_MODEL];
__device__ float g_ctx[(size_t)ROWS * D_MODEL];
__device__ float g_xr[(size_t)ROWS * D_MODEL];          // tf32-rounded x
__device__ float g_wr[(size_t)4 * D_MODEL * D_MODEL];   // tf32-rounded Wq,Wk,Wv,Wo

// ---------------------------------------------------------------------------
// Base-ISA helpers (sm_80 class only — NO tcgen05 on this toolchain target)
// ---------------------------------------------------------------------------
__device__ __forceinline__ uint32_t smem_u32(const void* p) {
    uint32_t a;
    asm("{ .reg .u64 t; cvta.to.shared.u64 t, %1; cvt.u32.u64 %0, t; }"
        : "=r"(a) : "l"(p));
    return a;
}
__device__ __forceinline__ uint32_t f2tf32(float x) {
    uint32_t u;
    asm("cvt.rna.tf32.f32 %0, %1;" : "=r"(u) : "f"(x));
    return u;
}
__device__ __forceinline__ float rnd_tf32(float x) {
    return __uint_as_float(f2tf32(x));
}
__device__ __forceinline__ void mma8(float* c, const uint32_t* a,
                                     uint32_t b0, uint32_t b1) {
    asm volatile(
        "mma.sync.aligned.m16n8k8.row.col.f32.tf32.tf32.f32 "
        "{%0,%1,%2,%3}, {%4,%5,%6,%7}, {%8,%9}, {%0,%1,%2,%3};"
        : "+f"(c[0]), "+f"(c[1]), "+f"(c[2]), "+f"(c[3])
        : "r"(a[0]), "r"(a[1]), "r"(a[2]), "r"(a[3]), "r"(b0), "r"(b1));
}
__device__ __forceinline__ void cp_async16(uint32_t dst, const void* src) {
    asm volatile("cp.async.cg.shared.global [%0], [%1], 16;"
                 :: "r"(dst), "l"(src));
}
#define CP_COMMIT() asm volatile("cp.async.commit_group;" ::: "memory")
#define CP_WAIT(n)  asm volatile("cp.async.wait_group %0;" :: "n"(n) : "memory")

// ---------------------------------------------------------------------------
// Pre-round pass: write tf32(rna)-rounded copies (low 13 mantissa bits = 0),
// so GEMM/attention can consume raw fp32 bits as valid tf32 operands.
// ---------------------------------------------------------------------------
__global__ void pre_round(const float4* __restrict__ s, float4* __restrict__ d,
                          int n4) {
    int i = blockIdx.x * blockDim.x + threadIdx.x;
    if (i < n4) {
        float4 v = s[i];
        d[i] = make_float4(rnd_tf32(v.x), rnd_tf32(v.y),
                           rnd_tf32(v.z), rnd_tf32(v.w));
    }
}

// ---------------------------------------------------------------------------
// TF32 GEMM v3: C[m][n] = sum_k A[m][k] * W[n][k]  (x @ W^T)
// Inputs pre-rounded to tf32. CTA 128x128, 4 warps (warp tile 64x64),
// k-chunk 32, 3-stage cp.async pipeline, 1 LDS instr per MMA.
// round_out=1: outputs tf32-rounded (and row-scaled) for downstream mma use.
// ---------------------------------------------------------------------------
#define LDA 36
#define TILEW (128*LDA)         // 4608 words
#define BUFW  (2*TILEW)         // 9216 words (A+B)
#define NST 3
#define GEMM_SMEM (NST*BUFW*4)  // 110592 bytes

__global__ __launch_bounds__(128, 2) void gemm_tf32p(
    const float* __restrict__ A,
    const float* __restrict__ W0, const float* __restrict__ W1, const float* __restrict__ W2,
    float* __restrict__ C0, float* __restrict__ C1, float* __restrict__ C2,
    float q_scale, int round_out)
{
    extern __shared__ uint32_t sm[];
    const float* W;
    float* C;
    if (blockIdx.z == 0)      { W = W0; C = C0; }
    else if (blockIdx.z == 1) { W = W1; C = C1; }
    else                      { W = W2; C = C2; }
    const float scale = (blockIdx.z == 0) ? q_scale : 1.0f;

    const int tid = threadIdx.x;
    const int w = tid >> 5, l = tid & 31;
    const int g = l >> 2, t = l & 3;
    const int bm = blockIdx.y * 128;
    const int bn = blockIdx.x * 128;
    const int wm = (w & 1) * 64;
    const int wn = (w >> 1) * 64;
    const int rsub = l >> 3, c16 = l & 7;   // fill mapping

    const float* Abase = A + (size_t)bm * D_MODEL;
    const float* Wbase = W + (size_t)bn * D_MODEL;
    const uint32_t smb = smem_u32(sm);

    auto FILL = [&](int chunk, int st) {
        uint32_t ab = smb + st * (BUFW * 4);
        uint32_t bb = ab + TILEW * 4;
#pragma unroll
        for (int it = 0; it < 8; it++) {
            int row = w * 32 + it * 4 + rsub;
            uint32_t doff = (uint32_t)(row * LDA + c16 * 4) * 4;
            size_t soff = (size_t)row * D_MODEL + chunk * 32 + c16 * 4;
            cp_async16(ab + doff, Abase + soff);
            cp_async16(bb + doff, Wbase + soff);
        }
    };

    float acc[4][8][4];
#pragma unroll
    for (int i = 0; i < 4; i++)
#pragma unroll
        for (int j = 0; j < 8; j++)
#pragma unroll
            for (int q = 0; q < 4; q++) acc[i][j][q] = 0.f;

    FILL(0, 0); CP_COMMIT();
    FILL(1, 1); CP_COMMIT();
    FILL(2, 2); CP_COMMIT();

    const int NCH = D_MODEL / 32;   // 32
    for (int c = 0; c < NCH; c++) {
        CP_WAIT(2);                 // chunk c's group complete
        __syncthreads();
        const int st = c % NST;
        const uint32_t* Ab = sm + st * BUFW;
        const uint32_t* Bb = Ab + TILEW;
#pragma unroll
        for (int s8 = 0; s8 < 4; s8++) {
            uint32_t a[4][4];
#pragma unroll
            for (int i = 0; i < 4; i++) {
                const uint32_t* p = Ab + (wm + i * 16 + g) * LDA + s8 * 8 + t;
                a[i][0] = p[0];
                a[i][1] = p[8 * LDA];
                a[i][2] = p[4];
                a[i][3] = p[8 * LDA + 4];
            }
#pragma unroll
            for (int j = 0; j < 8; j++) {
                const uint32_t* p = Bb + (wn + j * 8 + g) * LDA + s8 * 8 + t;
                uint32_t b0 = p[0], b1 = p[4];
#pragma unroll
                for (int i = 0; i < 4; i++) mma8(acc[i][j], a[i], b0, b1);
            }
        }
        __syncthreads();            // all warps done reading stage st
        if (c + NST < NCH) FILL(c + NST, st);
        CP_COMMIT();                // commit (possibly empty) to keep count
    }

    // Epilogue
#pragma unroll
    for (int i = 0; i < 4; i++) {
        int r0 = bm + wm + i * 16 + g;
#pragma unroll
        for (int j = 0; j < 8; j++) {
            int col = bn + wn + j * 8 + 2 * t;
            float v0 = acc[i][j][0] * scale, v1 = acc[i][j][1] * scale;
            float v2 = acc[i][j][2] * scale, v3 = acc[i][j][3] * scale;
            if (round_out) {
                v0 = rnd_tf32(v0); v1 = rnd_tf32(v1);
                v2 = rnd_tf32(v2); v3 = rnd_tf32(v3);
            }
            *(float2*)(C + (size_t)r0 * D_MODEL + col) = make_float2(v0, v1);
            *(float2*)(C + (size_t)(r0 + 8) * D_MODEL + col) = make_float2(v2, v3);
        }
    }
}

// ---------------------------------------------------------------------------
// Fused causal attention v2 on tf32 mma. CTA = (b, h, 128 q rows), 4 warps,
// warp owns 32 score rows (2 m16 tiles) end-to-end; softmax in registers.
// q/k/v are pre-rounded tf32 (Q pre-scaled by 0.125) -> fills are raw copies
// (Q/K via cp.async). kt iterates 64-wide K/V tiles.
// ---------------------------------------------------------------------------
#define AP 68
#define ATTN_SMEM ((128+64+128+64)*AP*4)   // 104448 bytes

__global__ __launch_bounds__(128, 2) void attn_tc()
{
    extern __shared__ uint32_t sm[];
    uint32_t* Qs = sm;                        // [128][AP]
    uint32_t* Ks = sm + 128 * AP;             // [64][AP]
    uint32_t* Ps = sm + (128 + 64) * AP;      // [128][AP]
    uint32_t* Vt = sm + (128 + 64 + 128) * AP;// [64][AP] transposed [dd][n]

    const int tid = threadIdx.x;
    const int w = tid >> 5, l = tid & 31;
    const int g = l >> 2, t = l & 3;
    const int qt = blockIdx.x, h = blockIdx.y, b = blockIdx.z;

    const size_t base = (size_t)b * SEQ * D_MODEL + (size_t)h * DK;
    const float* qg = g_q + base + (size_t)qt * 128 * D_MODEL;
    const float* kg = g_k + base;
    const float* vg = g_v + base;

    const uint32_t smb = smem_u32(sm);
    const uint32_t Ks_b = smb + 128 * AP * 4;

    // Q fill: 128 rows x 64 floats, raw cp.async (pre-rounded, pre-scaled)
#pragma unroll
    for (int it = 0; it < 16; it++) {
        int flat = tid + it * 128;
        int m = flat >> 4, c4 = flat & 15;
        cp_async16(smb + (uint32_t)(m * AP + c4 * 4) * 4,
                   qg + (size_t)m * D_MODEL + c4 * 4);
    }
    CP_COMMIT();

    const int rbase = w * 32;
    float mr[4] = {-1e30f, -1e30f, -1e30f, -1e30f};
    float lr[4] = {0.f, 0.f, 0.f, 0.f};
    float acco[2][8][4];
#pragma unroll
    for (int mt = 0; mt < 2; mt++)
#pragma unroll
        for (int j = 0; j < 8; j++)
#pragma unroll
            for (int q = 0; q < 4; q++) acco[mt][j][q] = 0.f;

    const uint32_t* kfb = Ks + g * AP + t;
    const uint32_t* vfb = Vt + g * AP + t;

    const int KT = 2 * qt + 1;
    for (int kt = 0; kt <= KT; kt++) {
        __syncthreads();   // previous iteration done with Ks/Vt

        // K fill: 64 rows x 64 floats, raw cp.async
        const float* kg_t = kg + (size_t)kt * 64 * D_MODEL;
#pragma unroll
        for (int it = 0; it < 8; it++) {
            int flat = tid + it * 128;
            int n = flat >> 4, c4 = flat & 15;
            cp_async16(Ks_b + (uint32_t)(n * AP + c4 * 4) * 4,
                       kg_t + (size_t)n * D_MODEL + c4 * 4);
        }
        CP_COMMIT();

        // V transposed fill via 4x4 register blocks (raw bits, pre-rounded)
        const float* vg_t = vg + (size_t)kt * 64 * D_MODEL;
#pragma unroll
        for (int it = 0; it < 2; it++) {
            int bidx = tid + it * 128;
            int dd4 = bidx & 15;
            int ng = bidx >> 4;
            float4 r[4];
#pragma unroll
            for (int i = 0; i < 4; i++)
                r[i] = *(const float4*)(vg_t + (size_t)(ng * 4 + i) * D_MODEL + dd4 * 4);
            float* rf = (float*)r;
#pragma unroll
            for (int u = 0; u < 4; u++) {
                *(uint4*)(Vt + (dd4 * 4 + u) * AP + ng * 4) = make_uint4(
                    __float_as_uint(rf[0 * 4 + u]), __float_as_uint(rf[1 * 4 + u]),
                    __float_as_uint(rf[2 * 4 + u]), __float_as_uint(rf[3 * 4 + u]));
            }
        }
        CP_WAIT(0);
        __syncthreads();

        // ---- S = Q K^T : warp computes 32x64 ----
        float accs[2][8][4];
#pragma unroll
        for (int mt = 0; mt < 2; mt++)
#pragma unroll
            for (int j = 0; j < 8; j++)
#pragma unroll
                for (int q = 0; q < 4; q++) accs[mt][j][q] = 0.f;

        const uint32_t* qfb0 = Qs + (rbase + g) * AP + t;
        const uint32_t* qfb1 = Qs + (rbase + 16 + g) * AP + t;
#pragma unroll
        for (int kc = 0; kc < 8; kc++) {
            uint32_t a0[4], a1[4];
            a0[0] = qfb0[kc * 8];     a0[1] = qfb0[8 * AP + kc * 8];
            a0[2] = qfb0[kc * 8 + 4]; a0[3] = qfb0[8 * AP + kc * 8 + 4];
            a1[0] = qfb1[kc * 8];     a1[1] = qfb1[8 * AP + kc * 8];
            a1[2] = qfb1[kc * 8 + 4]; a1[3] = qfb1[8 * AP + kc * 8 + 4];
#pragma unroll
            for (int j = 0; j < 8; j++) {
                const uint32_t* bp = kfb + (j * 8) * AP + kc * 8;
                uint32_t b0 = bp[0], b1 = bp[4];
                mma8(accs[0][j], a0, b0, b1);
                mma8(accs[1][j], a1, b0, b1);
            }
        }

        // ---- causal mask (last two tiles only) ----
        const int off = qt * 128 - kt * 64;
        if (off < 64) {
#pragma unroll
            for (int mt = 0; mt < 2; mt++)
#pragma unroll
                for (int j = 0; j < 8; j++) {
                    int r0 = rbase + mt * 16 + g;
                    int c0 = j * 8 + 2 * t;
                    if (c0 > off + r0)     accs[mt][j][0] = -1e30f;
                    if (c0 + 1 > off + r0) accs[mt][j][1] = -1e30f;
                    if (c0 > off + r0 + 8)     accs[mt][j][2] = -1e30f;
                    if (c0 + 1 > off + r0 + 8) accs[mt][j][3] = -1e30f;
                }
        }

        // ---- online softmax (4 row-groups per thread) ----
#pragma unroll
        for (int mt = 0; mt < 2; mt++) {
            float mxA = -1e30f, mxB = -1e30f;
#pragma unroll
            for (int j = 0; j < 8; j++) {
                mxA = fmaxf(mxA, fmaxf(accs[mt][j][0], accs[mt][j][1]));
                mxB = fmaxf(mxB, fmaxf(accs[mt][j][2], accs[mt][j][3]));
            }
            mxA = fmaxf(mxA, __shfl_xor_sync(0xffffffffu, mxA, 1));
            mxA = fmaxf(mxA, __shfl_xor_sync(0xffffffffu, mxA, 2));
            mxB = fmaxf(mxB, __shfl_xor_sync(0xffffffffu, mxB, 1));
            mxB = fmaxf(mxB, __shfl_xor_sync(0xffffffffu, mxB, 2));

            const int gA = 2 * mt, gB = 2 * mt + 1;
            float mnA = fmaxf(mr[gA], mxA), mnB = fmaxf(mr[gB], mxB);
            float alA = __expf(mr[gA] - mnA), alB = __expf(mr[gB] - mnB);
            mr[gA] = mnA; mr[gB] = mnB;

            float sA = 0.f, sB = 0.f;
#pragma unroll
            for (int j = 0; j < 8; j++) {
                accs[mt][j][0] = __expf(accs[mt][j][0] - mnA);
                accs[mt][j][1] = __expf(accs[mt][j][1] - mnA);
                accs[mt][j][2] = __expf(accs[mt][j][2] - mnB);
                accs[mt][j][3] = __expf(accs[mt][j][3] - mnB);
                sA += accs[mt][j][0] + accs[mt][j][1];
                sB += accs[mt][j][2] + accs[mt][j][3];
            }
            sA += __shfl_xor_sync(0xffffffffu, sA, 1);
            sA += __shfl_xor_sync(0xffffffffu, sA, 2);
            sB += __shfl_xor_sync(0xffffffffu, sB, 1);
            sB += __shfl_xor_sync(0xffffffffu, sB, 2);
            lr[gA] = lr[gA] * alA + sA;
            lr[gB] = lr[gB] * alB + sB;

#pragma unroll
            for (int j = 0; j < 8; j++) {
                acco[mt][j][0] *= alA; acco[mt][j][1] *= alA;
                acco[mt][j][2] *= alB; acco[mt][j][3] *= alB;
            }

            // store P rows (own warp only) as tf32
            uint32_t* psb = Ps + (rbase + mt * 16 + g) * AP;
#pragma unroll
            for (int j = 0; j < 8; j++) {
                *(uint2*)(psb + j * 8 + 2 * t) =
                    make_uint2(f2tf32(accs[mt][j][0]), f2tf32(accs[mt][j][1]));
                *(uint2*)(psb + 8 * AP + j * 8 + 2 * t) =
                    make_uint2(f2tf32(accs[mt][j][2]), f2tf32(accs[mt][j][3]));
            }
        }
        __syncwarp();

        // ---- O += P V ----
        const uint32_t* pfb0 = Ps + (rbase + g) * AP + t;
        const uint32_t* pfb1 = Ps + (rbase + 16 + g) * AP + t;
#pragma unroll
        for (int kc = 0; kc < 8; kc++) {
            uint32_t a0[4], a1[4];
            a0[0] = pfb0[kc * 8];     a0[1] = pfb0[8 * AP + kc * 8];
            a0[2] = pfb0[kc * 8 + 4]; a0[3] = pfb0[8 * AP + kc * 8 + 4];
            a1[0] = pfb1[kc * 8];     a1[1] = pfb1[8 * AP + kc * 8];
            a1[2] = pfb1[kc * 8 + 4]; a1[3] = pfb1[8 * AP + kc * 8 + 4];
#pragma unroll
            for (int j = 0; j < 8; j++) {
                const uint32_t* bp = vfb + (j * 8) * AP + kc * 8;
                uint32_t b0 = bp[0], b1 = bp[4];
                mma8(acco[0][j], a0, b0, b1);
                mma8(acco[1][j], a1, b0, b1);
            }
        }
        __syncwarp();   // P reads done before next iteration's stores
    }

    // Epilogue: normalize, tf32-round (feeds O-projection mma), write ctx
    float* og = g_ctx + base;
#pragma unroll
    for (int mt = 0; mt < 2; mt++) {
        float invA = 1.f / lr[2 * mt], invB = 1.f / lr[2 * mt + 1];
        size_t rA = (size_t)(qt * 128 + rbase + mt * 16 + g) * D_MODEL;
        size_t rB = rA + (size_t)8 * D_MODEL;
#pragma unroll
        for (int j = 0; j < 8; j++) {
            int col = j * 8 + 2 * t;
            *(float2*)(og + rA + col) = make_float2(
                rnd_tf32(acco[mt][j][0] * invA), rnd_tf32(acco[mt][j][1] * invA));
            *(float2*)(og + rB + col) = make_float2(
                rnd_tf32(acco[mt][j][2] * invB), rnd_tf32(acco[mt][j][3] * invB));
        }
    }
}

// ---------------------------------------------------------------------------
// Launch
// ---------------------------------------------------------------------------
extern "C" void kernel_launch(void* const* d_in, const int* in_sizes, int n_in,
                              void* d_out, int out_size)
{
    (void)in_sizes; (void)n_in; (void)out_size;
    const float* x  = (const float*)d_in[0];
    const float* Wq = (const float*)d_in[1];
    const float* Wk = (const float*)d_in[2];
    const float* Wv = (const float*)d_in[3];
    const float* Wo = (const float*)d_in[4];
    float* out = (float*)d_out;

    float *qp, *kp, *vp, *cp, *xr, *wr;
    cudaGetSymbolAddress((void**)&qp, g_q);
    cudaGetSymbolAddress((void**)&kp, g_k);
    cudaGetSymbolAddress((void**)&vp, g_v);
    cudaGetSymbolAddress((void**)&cp, g_ctx);
    cudaGetSymbolAddress((void**)&xr, g_xr);
    cudaGetSymbolAddress((void**)&wr, g_wr);

    cudaFuncSetAttribute(gemm_tf32p, cudaFuncAttributeMaxDynamicSharedMemorySize,
                         GEMM_SMEM);
    cudaFuncSetAttribute(attn_tc, cudaFuncAttributeMaxDynamicSharedMemorySize,
                         ATTN_SMEM);

    const int NX4 = ROWS * D_MODEL / 4;          // 2097152
    const int NW4 = D_MODEL * D_MODEL / 4;       // 262144
    const size_t WSZ = (size_t)D_MODEL * D_MODEL;
    pre_round<<<(NX4 + 255) / 256, 256>>>((const float4*)x, (float4*)xr, NX4);
    pre_round<<<(NW4 + 255) / 256, 256>>>((const float4*)Wq, (float4*)(wr + 0 * WSZ), NW4);
    pre_round<<<(NW4 + 255) / 256, 256>>>((const float4*)Wk, (float4*)(wr + 1 * WSZ), NW4);
    pre_round<<<(NW4 + 255) / 256, 256>>>((const float4*)Wv, (float4*)(wr + 2 * WSZ), NW4);
    pre_round<<<(NW4 + 255) / 256, 256>>>((const float4*)Wo, (float4*)(wr + 3 * WSZ), NW4);

    // QKV projections (z picks weight); Q rows pre-scaled by 1/sqrt(dk) and
    // outputs tf32-rounded for the attention mma stage.
    dim3 gproj(D_MODEL / 128, ROWS / 128, 3);
    gemm_tf32p<<<gproj, 128, GEMM_SMEM>>>(xr, wr + 0 * WSZ, wr + 1 * WSZ, wr + 2 * WSZ,
                                          qp, kp, vp, 0.125f, 1);

    // Causal attention (tf32 mma, 128-row q tiles)
    dim3 gattn(SEQ / 128, NHEAD, BATCH);
    attn_tc<<<gattn, 128, ATTN_SMEM>>>();

    // Output projection (full-precision fp32 output)
    dim3 gout(D_MODEL / 128, ROWS / 128, 1);
    gemm_tf32p<<<gout, 128, GEMM_SMEM>>>(cp, wr + 3 * WSZ, wr + 3 * WSZ, wr + 3 * WSZ,
                                         out, out, out, 1.0f, 0);
}